// round 5
// baseline (speedup 1.0000x reference)
#include <cuda_runtime.h>
#include <cuda_bf16.h>
#include <math.h>
#include <stdint.h>

// Attention_33492154974379:  x [B=8, T=2048, D=1024] fp32
// out = concat(att_vec [B,T,D], att_weights [B,T,T])
// R5: mma.sync path (tcgen05 unavailable: ptxas target is sm_103, not 103a).
//     Block tile 128x256, warp tile 64x64 (8 warps) -> 1.5x fewer LDSM
//     bytes per HMMA vs R3's 64x32 warp tiles.

#define B_ 8
#define T_ 2048
#define D_ 1024
#define NEG_INF_ (-1.0e9f)

// ---- static scratch ----
__device__ __nv_bfloat16 g_xhi[(size_t)B_ * T_ * D_];
__device__ __nv_bfloat16 g_xlo[(size_t)B_ * T_ * D_];
__device__ __nv_bfloat16 g_xthi[(size_t)B_ * D_ * T_];   // x^T [B,D,T]
__device__ __nv_bfloat16 g_xtlo[(size_t)B_ * D_ * T_];
__device__ __nv_bfloat16 g_whi[(size_t)B_ * T_ * T_];
__device__ __nv_bfloat16 g_wlo[(size_t)B_ * T_ * T_];

// ---- smem: stage = Ahi(128x32) Alo(128x32) Bhi(256x32) Blo(256x32), stride 40
#define LDS_ 40
#define OFF_AHI 0
#define OFF_ALO 5120
#define OFF_BHI 10240
#define OFF_BLO 20480
#define STAGE_E 30720
#define SMEM_BYTES (2 * STAGE_E * 2)   // 122880 B, double buffered

__device__ __forceinline__ void ldsm4(uint32_t* r, uint32_t a) {
    asm volatile("ldmatrix.sync.aligned.m8n8.x4.shared.b16 {%0,%1,%2,%3}, [%4];"
                 : "=r"(r[0]), "=r"(r[1]), "=r"(r[2]), "=r"(r[3]) : "r"(a));
}
__device__ __forceinline__ void mma16816(float* d, const uint32_t* a, const uint32_t* b) {
    asm volatile("mma.sync.aligned.m16n8k16.row.col.f32.bf16.bf16.f32 "
                 "{%0,%1,%2,%3}, {%4,%5,%6,%7}, {%8,%9}, {%0,%1,%2,%3};"
                 : "+f"(d[0]), "+f"(d[1]), "+f"(d[2]), "+f"(d[3])
                 : "r"(a[0]), "r"(a[1]), "r"(a[2]), "r"(a[3]), "r"(b[0]), "r"(b[1]));
}
__device__ __forceinline__ void cpa16(uint32_t d, const void* s) {
    asm volatile("cp.async.cg.shared.global [%0], [%1], 16;" :: "r"(d), "l"(s) : "memory");
}
__device__ __forceinline__ void cpcommit() { asm volatile("cp.async.commit_group;" ::: "memory"); }
template <int N>
__device__ __forceinline__ void cpwait() { asm volatile("cp.async.wait_group %0;" :: "n"(N) : "memory"); }

// ---------------------------------------------------------------------------
// Pass 0: x -> (hi,lo) and transposed (hi,lo)
// ---------------------------------------------------------------------------
__global__ __launch_bounds__(256) void convert_kernel(const float* __restrict__ x) {
    __shared__ float tile[32][33];
    const int b = blockIdx.z;
    const int t0 = blockIdx.y * 32, d0 = blockIdx.x * 32;
    const int tx = threadIdx.x, ty = threadIdx.y;  // (32, 8)
    const float* xb = x + (size_t)b * T_ * D_;

    #pragma unroll
    for (int k = 0; k < 4; ++k) {
        const int r = ty + k * 8;
        const float v = xb[(size_t)(t0 + r) * D_ + d0 + tx];
        tile[r][tx] = v;
        __nv_bfloat16 hi = __float2bfloat16_rn(v);
        __nv_bfloat16 lo = __float2bfloat16_rn(v - __bfloat162float(hi));
        const size_t o = (size_t)b * T_ * D_ + (size_t)(t0 + r) * D_ + d0 + tx;
        g_xhi[o] = hi; g_xlo[o] = lo;
    }
    __syncthreads();
    #pragma unroll
    for (int k = 0; k < 4; ++k) {
        const int r = ty + k * 8;
        const float v = tile[tx][r];
        __nv_bfloat16 hi = __float2bfloat16_rn(v);
        __nv_bfloat16 lo = __float2bfloat16_rn(v - __bfloat162float(hi));
        const size_t o = (size_t)b * D_ * T_ + (size_t)(d0 + r) * T_ + t0 + tx;
        g_xthi[o] = hi; g_xtlo[o] = lo;
    }
}

// ---------------------------------------------------------------------------
// Fill one K=32 stage. 12 cp.async x 16B per thread (256 thr).
// ---------------------------------------------------------------------------
static __device__ __forceinline__ void fill_stage(
    uint32_t stage, const __nv_bfloat16* __restrict__ Ahi,
    const __nv_bfloat16* __restrict__ Alo, const __nv_bfloat16* __restrict__ Bhi,
    const __nv_bfloat16* __restrict__ Blo, int ldk, int kk, int tid)
{
    const int r0 = tid >> 2;                 // 0..63
    const int c  = tid & 3;                  // 16B chunk in row
    const uint32_t cb = (uint32_t)(c * 8) * 2;
    #pragma unroll
    for (int j = 0; j < 2; ++j) {
        const int lr = r0 + 64 * j;
        const size_t go = (size_t)lr * ldk + kk + c * 8;
        cpa16(stage + (uint32_t)(OFF_AHI + lr * LDS_) * 2 + cb, Ahi + go);
        cpa16(stage + (uint32_t)(OFF_ALO + lr * LDS_) * 2 + cb, Alo + go);
    }
    #pragma unroll
    for (int j = 0; j < 4; ++j) {
        const int lr = r0 + 64 * j;
        const size_t go = (size_t)lr * ldk + kk + c * 8;
        cpa16(stage + (uint32_t)(OFF_BHI + lr * LDS_) * 2 + cb, Bhi + go);
        cpa16(stage + (uint32_t)(OFF_BLO + lr * LDS_) * 2 + cb, Blo + go);
    }
}

// ---------------------------------------------------------------------------
// Mainloop: C[128x256] += 3-term split GEMM over K (chunks of 32).
// Warp grid 2x4, warp tile 64x64. acc[4][8][4].
// ---------------------------------------------------------------------------
static __device__ __forceinline__ void gemm_mainloop(
    const __nv_bfloat16* __restrict__ Ahi, const __nv_bfloat16* __restrict__ Alo,
    const __nv_bfloat16* __restrict__ Bhi, const __nv_bfloat16* __restrict__ Blo,
    int ldk, int kmax, float acc[4][8][4])
{
    extern __shared__ __nv_bfloat16 sm[];
    const int tid = threadIdx.x;
    const int lane = tid & 31, warp = tid >> 5;
    const int wm = (warp >> 2) * 64, wn = (warp & 3) * 64;
    const uint32_t smem_u32 = (uint32_t)__cvta_generic_to_shared(sm);

    const int nchunks = kmax >> 5;

    fill_stage(smem_u32, Ahi, Alo, Bhi, Blo, ldk, 0, tid);
    cpcommit();
    fill_stage(smem_u32 + STAGE_E * 2, Ahi, Alo, Bhi, Blo, ldk, 32, tid);
    cpcommit();

    for (int i = 0; i < nchunks; ++i) {
        const int s = i & 1;
        if (i + 1 < nchunks) cpwait<1>(); else cpwait<0>();
        __syncthreads();

        const uint32_t st    = smem_u32 + (uint32_t)(s * STAGE_E) * 2;
        const uint32_t stAhi = st + OFF_AHI * 2;
        const uint32_t stAlo = st + OFF_ALO * 2;
        const uint32_t stBhi = st + OFF_BHI * 2;
        const uint32_t stBlo = st + OFF_BLO * 2;

        #pragma unroll
        for (int s2 = 0; s2 < 2; ++s2) {
            uint32_t ahi[4][4], alo[4][4], bhi[8][2], blo[8][2];
            const int ar = wm + (lane & 15);
            const int ac = ((lane >> 4) + 2 * s2) * 8;
            #pragma unroll
            for (int mt = 0; mt < 4; ++mt) {
                const uint32_t off = (uint32_t)((ar + mt * 16) * LDS_ + ac) * 2;
                ldsm4(ahi[mt], stAhi + off);
                ldsm4(alo[mt], stAlo + off);
            }
            const int br = wn + ((lane >> 4) & 1) * 8 + (lane & 7);
            const int bc = (((lane >> 3) & 1) + 2 * s2) * 8;
            #pragma unroll
            for (int p = 0; p < 4; ++p) {
                const uint32_t off = (uint32_t)((br + p * 16) * LDS_ + bc) * 2;
                uint32_t r4[4];
                ldsm4(r4, stBhi + off);
                bhi[2 * p][0] = r4[0]; bhi[2 * p][1] = r4[1];
                bhi[2 * p + 1][0] = r4[2]; bhi[2 * p + 1][1] = r4[3];
                ldsm4(r4, stBlo + off);
                blo[2 * p][0] = r4[0]; blo[2 * p][1] = r4[1];
                blo[2 * p + 1][0] = r4[2]; blo[2 * p + 1][1] = r4[3];
            }
            #pragma unroll
            for (int mt = 0; mt < 4; ++mt)
                #pragma unroll
                for (int nt = 0; nt < 8; ++nt) {
                    mma16816(acc[mt][nt], ahi[mt], bhi[nt]);
                    mma16816(acc[mt][nt], ahi[mt], blo[nt]);
                    mma16816(acc[mt][nt], alo[mt], bhi[nt]);
                }
        }
        __syncthreads();

        if (i + 2 < nchunks) {
            fill_stage(st, Ahi, Alo, Bhi, Blo, ldk, (i + 2) * 32, tid);
            cpcommit();
        }
    }
}

// ---------------------------------------------------------------------------
// Pass 1: masked scores (pre-softmax), tiles 128 rows x 256 cols
// ---------------------------------------------------------------------------
__global__ __launch_bounds__(256, 1) void scores_mma_kernel(float* __restrict__ w) {
    const int b = blockIdx.z, ti = blockIdx.y, tj = blockIdx.x;
    float* wb = w + (size_t)b * T_ * T_;
    const int gi0 = ti * 128, gj0 = tj * 256;
    const int tid = threadIdx.x;

    if (2 * tj > ti) {  // tile entirely above (or at) the diagonal band: mask fill
        const float4 nv = make_float4(NEG_INF_, NEG_INF_, NEG_INF_, NEG_INF_);
        #pragma unroll
        for (int t = 0; t < 32; ++t) {
            const int i = tid + t * 256;          // 8192 float4 slots
            const int r = i >> 6, c4 = i & 63;
            *(float4*)(wb + (size_t)(gi0 + r) * T_ + gj0 + c4 * 4) = nv;
        }
        return;
    }

    float acc[4][8][4] = {};
    const size_t ao = ((size_t)b * T_ + gi0) * D_;
    const size_t bo = ((size_t)b * T_ + gj0) * D_;
    gemm_mainloop(g_xhi + ao, g_xlo + ao, g_xhi + bo, g_xlo + bo, D_, D_, acc);

    const int lane = tid & 31, warp = tid >> 5;
    const int wm = (warp >> 2) * 64, wn = (warp & 3) * 64;
    const bool partial = (2 * tj + 1 >= ti);   // tile touches the diagonal
    #pragma unroll
    for (int mt = 0; mt < 4; ++mt)
        #pragma unroll
        for (int nt = 0; nt < 8; ++nt) {
            const int gi = gi0 + wm + mt * 16 + (lane >> 2);
            const int gj = gj0 + wn + nt * 8 + 2 * (lane & 3);
            float* p0 = wb + (size_t)gi * T_ + gj;
            float* p1 = wb + (size_t)(gi + 8) * T_ + gj;
            if (!partial) {
                p0[0] = acc[mt][nt][0]; p0[1] = acc[mt][nt][1];
                p1[0] = acc[mt][nt][2]; p1[1] = acc[mt][nt][3];
            } else {
                p0[0] = (gj     < gi    ) ? acc[mt][nt][0] : NEG_INF_;
                p0[1] = (gj + 1 < gi    ) ? acc[mt][nt][1] : NEG_INF_;
                p1[0] = (gj     < gi + 8) ? acc[mt][nt][2] : NEG_INF_;
                p1[1] = (gj + 1 < gi + 8) ? acc[mt][nt][3] : NEG_INF_;
            }
        }
}

// ---------------------------------------------------------------------------
// Pass 2: row softmax in place; also emit bf16 hi/lo of W
// ---------------------------------------------------------------------------
__global__ __launch_bounds__(256) void softmax_kernel(float* __restrict__ w) {
    const size_t row = blockIdx.x;
    float* p = w + row * T_;
    __nv_bfloat16* ph = g_whi + row * T_;
    __nv_bfloat16* pl = g_wlo + row * T_;
    const int tid = threadIdx.x;

    float v[8];
    float m = -INFINITY;
    #pragma unroll
    for (int k = 0; k < 8; ++k) { v[k] = p[tid + k * 256]; m = fmaxf(m, v[k]); }

    __shared__ float red[256];
    red[tid] = m; __syncthreads();
    #pragma unroll
    for (int s = 128; s > 0; s >>= 1) {
        if (tid < s) red[tid] = fmaxf(red[tid], red[tid + s]);
        __syncthreads();
    }
    m = red[0];
    __syncthreads();

    float sum = 0.0f;
    #pragma unroll
    for (int k = 0; k < 8; ++k) { v[k] = expf(v[k] - m); sum += v[k]; }

    red[tid] = sum; __syncthreads();
    #pragma unroll
    for (int s = 128; s > 0; s >>= 1) {
        if (tid < s) red[tid] += red[tid + s];
        __syncthreads();
    }
    const float inv = 1.0f / red[0];

    #pragma unroll
    for (int k = 0; k < 8; ++k) {
        const float val = v[k] * inv;
        p[tid + k * 256] = val;
        const __nv_bfloat16 hi = __float2bfloat16_rn(val);
        ph[tid + k * 256] = hi;
        pl[tid + k * 256] = __float2bfloat16_rn(val - __bfloat162float(hi));
    }
}

// ---------------------------------------------------------------------------
// Pass 3: att_vec = W @ X, tiles 128 x 256, K truncated by causal zeros
// ---------------------------------------------------------------------------
__global__ __launch_bounds__(256, 1) void av_mma_kernel(float* __restrict__ o) {
    const int b = blockIdx.z, ti = blockIdx.y, tj = blockIdx.x;
    const int gi0 = ti * 128, gj0 = tj * 256;
    const int kmax = (ti == 0) ? T_ : (ti + 1) * 128;  // row 0 dense (uniform 1/T)

    float acc[4][8][4] = {};
    const size_t ao = ((size_t)b * T_ + gi0) * T_;
    const size_t bo = ((size_t)b * D_ + gj0) * T_;
    gemm_mainloop(g_whi + ao, g_wlo + ao, g_xthi + bo, g_xtlo + bo, T_, kmax, acc);

    float* ob = o + (size_t)b * T_ * D_;
    const int tid = threadIdx.x;
    const int lane = tid & 31, warp = tid >> 5;
    const int wm = (warp >> 2) * 64, wn = (warp & 3) * 64;
    #pragma unroll
    for (int mt = 0; mt < 4; ++mt)
        #pragma unroll
        for (int nt = 0; nt < 8; ++nt) {
            const int gi = gi0 + wm + mt * 16 + (lane >> 2);
            const int gj = gj0 + wn + nt * 8 + 2 * (lane & 3);
            float* p0 = ob + (size_t)gi * D_ + gj;
            float* p1 = ob + (size_t)(gi + 8) * D_ + gj;
            p0[0] = acc[mt][nt][0]; p0[1] = acc[mt][nt][1];
            p1[0] = acc[mt][nt][2]; p1[1] = acc[mt][nt][3];
        }
}

// ---------------------------------------------------------------------------
extern "C" void kernel_launch(void* const* d_in, const int* in_sizes, int n_in,
                              void* d_out, int out_size) {
    const float* x = (const float*)d_in[0];
    float* att_vec = (float*)d_out;                          // [B,T,D]
    float* att_w   = (float*)d_out + (size_t)B_ * T_ * D_;   // [B,T,T]
    (void)in_sizes; (void)n_in; (void)out_size;

    cudaFuncSetAttribute(scores_mma_kernel, cudaFuncAttributeMaxDynamicSharedMemorySize, SMEM_BYTES);
    cudaFuncSetAttribute(av_mma_kernel, cudaFuncAttributeMaxDynamicSharedMemorySize, SMEM_BYTES);

    convert_kernel<<<dim3(D_ / 32, T_ / 32, B_), dim3(32, 8)>>>(x);
    scores_mma_kernel<<<dim3(T_ / 256, T_ / 128, B_), 256, SMEM_BYTES>>>(att_w);
    softmax_kernel<<<B_ * T_, 256>>>(att_w);
    av_mma_kernel<<<dim3(D_ / 256, T_ / 128, B_), 256, SMEM_BYTES>>>(att_vec);
}

// round 6
// speedup vs baseline: 1.0084x; 1.0084x over previous
#include <cuda_runtime.h>
#include <cuda_bf16.h>
#include <math.h>
#include <stdint.h>

// Attention_33492154974379:  x [B=8, T=2048, D=1024] fp32
// out = concat(att_vec [B,T,D], att_weights [B,T,T])
// R6: mma.sync path (legacy HMMA rate-bound ~48%) -> cut MACs:
//     row-0 analytic mean (av kmax=(ti+1)*128 for all tiles),
//     diagonal-block MMA skip in scores, prefix softmax.

#define B_ 8
#define T_ 2048
#define D_ 1024
#define NEG_INF_ (-1.0e9f)

// ---- static scratch ----
__device__ __nv_bfloat16 g_xhi[(size_t)B_ * T_ * D_];
__device__ __nv_bfloat16 g_xlo[(size_t)B_ * T_ * D_];
__device__ __nv_bfloat16 g_xthi[(size_t)B_ * D_ * T_];   // x^T [B,D,T]
__device__ __nv_bfloat16 g_xtlo[(size_t)B_ * D_ * T_];
__device__ __nv_bfloat16 g_whi[(size_t)B_ * T_ * T_];
__device__ __nv_bfloat16 g_wlo[(size_t)B_ * T_ * T_];
__device__ float g_r0[(size_t)B_ * 8 * D_];              // row-0 partial sums

// ---- smem: 4 tiles (Ahi,Alo,Bhi,Blo) of 128 x 32 bf16, stride 40 ----
#define LDS_ 40
#define TILE_E (128 * LDS_)
#define STAGE_E (4 * TILE_E)
#define SMEM_BYTES (2 * STAGE_E * 2)  // 81920 B double buffered

__device__ __forceinline__ void ldsm4(uint32_t* r, uint32_t a) {
    asm volatile("ldmatrix.sync.aligned.m8n8.x4.shared.b16 {%0,%1,%2,%3}, [%4];"
                 : "=r"(r[0]), "=r"(r[1]), "=r"(r[2]), "=r"(r[3]) : "r"(a));
}
__device__ __forceinline__ void mma16816(float* d, const uint32_t* a, const uint32_t* b) {
    asm volatile("mma.sync.aligned.m16n8k16.row.col.f32.bf16.bf16.f32 "
                 "{%0,%1,%2,%3}, {%4,%5,%6,%7}, {%8,%9}, {%0,%1,%2,%3};"
                 : "+f"(d[0]), "+f"(d[1]), "+f"(d[2]), "+f"(d[3])
                 : "r"(a[0]), "r"(a[1]), "r"(a[2]), "r"(a[3]), "r"(b[0]), "r"(b[1]));
}
__device__ __forceinline__ void cpa16(uint32_t d, const void* s) {
    asm volatile("cp.async.cg.shared.global [%0], [%1], 16;" :: "r"(d), "l"(s) : "memory");
}
__device__ __forceinline__ void cpcommit() { asm volatile("cp.async.commit_group;" ::: "memory"); }
template <int N>
__device__ __forceinline__ void cpwait() { asm volatile("cp.async.wait_group %0;" :: "n"(N) : "memory"); }

// ---------------------------------------------------------------------------
// Pass 0: x -> (hi,lo) and transposed (hi,lo)
// ---------------------------------------------------------------------------
__global__ __launch_bounds__(256) void convert_kernel(const float* __restrict__ x) {
    __shared__ float tile[32][33];
    const int b = blockIdx.z;
    const int t0 = blockIdx.y * 32, d0 = blockIdx.x * 32;
    const int tx = threadIdx.x, ty = threadIdx.y;  // (32, 8)
    const float* xb = x + (size_t)b * T_ * D_;

    #pragma unroll
    for (int k = 0; k < 4; ++k) {
        const int r = ty + k * 8;
        const float v = xb[(size_t)(t0 + r) * D_ + d0 + tx];
        tile[r][tx] = v;
        __nv_bfloat16 hi = __float2bfloat16_rn(v);
        __nv_bfloat16 lo = __float2bfloat16_rn(v - __bfloat162float(hi));
        const size_t o = (size_t)b * T_ * D_ + (size_t)(t0 + r) * D_ + d0 + tx;
        g_xhi[o] = hi; g_xlo[o] = lo;
    }
    __syncthreads();
    #pragma unroll
    for (int k = 0; k < 4; ++k) {
        const int r = ty + k * 8;
        const float v = tile[tx][r];
        __nv_bfloat16 hi = __float2bfloat16_rn(v);
        __nv_bfloat16 lo = __float2bfloat16_rn(v - __bfloat162float(hi));
        const size_t o = (size_t)b * D_ * T_ + (size_t)(d0 + r) * T_ + t0 + tx;
        g_xthi[o] = hi; g_xtlo[o] = lo;
    }
}

// ---------------------------------------------------------------------------
// Shared MMA mainloop: C[128x128] += 3-term split GEMM over K (chunks of 32).
// diag=true: skip accumulator blocks entirely above the diagonal (gi0==gj0).
// ---------------------------------------------------------------------------
__device__ __forceinline__ void gemm_mainloop(
    const __nv_bfloat16* __restrict__ Ahi, const __nv_bfloat16* __restrict__ Alo,
    const __nv_bfloat16* __restrict__ Bhi, const __nv_bfloat16* __restrict__ Blo,
    int ldk, int kmax, float acc[4][4][4], bool diag)
{
    extern __shared__ __nv_bfloat16 sm[];
    const int tid = threadIdx.x;
    const int lane = tid & 31, warp = tid >> 5;
    const int wm = (warp >> 2) * 64, wn = (warp & 3) * 32;
    const uint32_t smem_u32 = (uint32_t)__cvta_generic_to_shared(sm);

    const int tile = tid >> 6;
    const __nv_bfloat16* sp = (tile == 0) ? Ahi : (tile == 1) ? Alo : (tile == 2) ? Bhi : Blo;
    const int crow0 = (tid & 63) >> 2;
    const int cc = tid & 3;
    const uint32_t dtile = (uint32_t)(tile * TILE_E) * 2;

    const int nchunks = kmax >> 5;

    {
        #pragma unroll
        for (int t = 0; t < 8; ++t) {
            const int row = crow0 + t * 16;
            cpa16(smem_u32 + dtile + (uint32_t)(row * LDS_ + cc * 8) * 2,
                  sp + (size_t)row * ldk + cc * 8);
        }
        cpcommit();
    }

    for (int i = 0; i < nchunks; ++i) {
        const int s = i & 1;
        if (i + 1 < nchunks) {
            const int kk = (i + 1) << 5;
            const uint32_t dst0 = smem_u32 + (uint32_t)((s ^ 1) * STAGE_E) * 2 + dtile;
            #pragma unroll
            for (int t = 0; t < 8; ++t) {
                const int row = crow0 + t * 16;
                cpa16(dst0 + (uint32_t)(row * LDS_ + cc * 8) * 2,
                      sp + (size_t)row * ldk + kk + cc * 8);
            }
            cpcommit();
            cpwait<1>();
        } else {
            cpwait<0>();
        }
        __syncthreads();

        const uint32_t stA   = smem_u32 + (uint32_t)(s * STAGE_E) * 2;
        const uint32_t stAlo = stA + TILE_E * 2;
        const uint32_t stB   = stA + 2 * TILE_E * 2;
        const uint32_t stBlo = stA + 3 * TILE_E * 2;

        #pragma unroll
        for (int s2 = 0; s2 < 2; ++s2) {
            uint32_t ahi[4][4], alo[4][4], bhi[4][2], blo[4][2];
            const int ar = wm + (lane & 15);
            const int ac = ((lane >> 4) + 2 * s2) * 8;
            #pragma unroll
            for (int mt = 0; mt < 4; ++mt) {
                const uint32_t off = (uint32_t)((ar + mt * 16) * LDS_ + ac) * 2;
                ldsm4(ahi[mt], stA + off);
                ldsm4(alo[mt], stAlo + off);
            }
            const int br = wn + ((lane >> 4) & 1) * 8 + (lane & 7);
            const int bc = (((lane >> 3) & 1) + 2 * s2) * 8;
            #pragma unroll
            for (int p = 0; p < 2; ++p) {
                const uint32_t off = (uint32_t)((br + p * 16) * LDS_ + bc) * 2;
                uint32_t r4[4];
                ldsm4(r4, stB + off);
                bhi[2 * p][0] = r4[0]; bhi[2 * p][1] = r4[1];
                bhi[2 * p + 1][0] = r4[2]; bhi[2 * p + 1][1] = r4[3];
                ldsm4(r4, stBlo + off);
                blo[2 * p][0] = r4[0]; blo[2 * p][1] = r4[1];
                blo[2 * p + 1][0] = r4[2]; blo[2 * p + 1][1] = r4[3];
            }
            #pragma unroll
            for (int mt = 0; mt < 4; ++mt)
                #pragma unroll
                for (int nt = 0; nt < 4; ++nt) {
                    // On diagonal tiles, blocks fully above the strict-lower
                    // region contribute nothing (store path writes -1e9).
                    if (diag && (wn + nt * 8 > wm + mt * 16 + 14)) continue;
                    mma16816(acc[mt][nt], ahi[mt], bhi[nt]);
                    mma16816(acc[mt][nt], ahi[mt], blo[nt]);
                    mma16816(acc[mt][nt], alo[mt], bhi[nt]);
                }
        }
        __syncthreads();
    }
}

// ---------------------------------------------------------------------------
// Pass 1: masked scores. Upper tiles get final W=0.0f (softmax skips them).
// ---------------------------------------------------------------------------
__global__ __launch_bounds__(256, 2) void scores_mma_kernel(float* __restrict__ w) {
    const int b = blockIdx.z, ti = blockIdx.y, tj = blockIdx.x;
    float* wb = w + (size_t)b * T_ * T_;
    const int gi0 = ti * 128, gj0 = tj * 128;
    const int tid = threadIdx.x;

    if (tj > ti) {  // fully masked tile: write FINAL weight value 0.0f
        const float4 zv = make_float4(0.0f, 0.0f, 0.0f, 0.0f);
        #pragma unroll
        for (int t = 0; t < 16; ++t) {
            const int i = tid + t * 256;
            const int r = i >> 5, c4 = i & 31;
            *(float4*)(wb + (size_t)(gi0 + r) * T_ + gj0 + c4 * 4) = zv;
        }
        return;
    }

    float acc[4][4][4] = {};
    const size_t ao = ((size_t)b * T_ + gi0) * D_;
    const size_t bo = ((size_t)b * T_ + gj0) * D_;
    const bool diag = (ti == tj);
    gemm_mainloop(g_xhi + ao, g_xlo + ao, g_xhi + bo, g_xlo + bo, D_, D_, acc, diag);

    const int lane = tid & 31, warp = tid >> 5;
    const int wm = (warp >> 2) * 64, wn = (warp & 3) * 32;
    #pragma unroll
    for (int mt = 0; mt < 4; ++mt)
        #pragma unroll
        for (int nt = 0; nt < 4; ++nt) {
            const int gi = gi0 + wm + mt * 16 + (lane >> 2);
            const int gj = gj0 + wn + nt * 8 + 2 * (lane & 3);
            float* p0 = wb + (size_t)gi * T_ + gj;
            float* p1 = wb + (size_t)(gi + 8) * T_ + gj;
            if (!diag) {
                p0[0] = acc[mt][nt][0]; p0[1] = acc[mt][nt][1];
                p1[0] = acc[mt][nt][2]; p1[1] = acc[mt][nt][3];
            } else {
                p0[0] = (gj     < gi    ) ? acc[mt][nt][0] : NEG_INF_;
                p0[1] = (gj + 1 < gi    ) ? acc[mt][nt][1] : NEG_INF_;
                p1[0] = (gj     < gi + 8) ? acc[mt][nt][2] : NEG_INF_;
                p1[1] = (gj + 1 < gi + 8) ? acc[mt][nt][3] : NEG_INF_;
            }
        }
}

// ---------------------------------------------------------------------------
// Pass 2: prefix softmax. Row i only touches k < roundup(i+1,128).
// Row 0: uniform 1/T over the full row (matches reference all -1e9 row).
// ---------------------------------------------------------------------------
__global__ __launch_bounds__(256) void softmax_kernel(float* __restrict__ w) {
    const int b = blockIdx.y;
    const int i = blockIdx.x;
    const size_t row = (size_t)b * T_ + i;
    float* p = w + row * T_;
    __nv_bfloat16* ph = g_whi + row * T_;
    __nv_bfloat16* pl = g_wlo + row * T_;
    const int tid = threadIdx.x;

    if (i == 0) {
        const float val = 1.0f / (float)T_;
        const __nv_bfloat16 hi = __float2bfloat16_rn(val);
        const __nv_bfloat16 lo = __float2bfloat16_rn(val - __bfloat162float(hi));
        for (int k = tid; k < T_; k += 256) { p[k] = val; ph[k] = hi; pl[k] = lo; }
        return;
    }

    const int L = (((i >> 7) + 1) << 7);   // 128..2048, multiple of 128

    __shared__ float red[256];
    float m = -INFINITY;
    for (int k = tid; k < L; k += 256) m = fmaxf(m, p[k]);
    red[tid] = m; __syncthreads();
    #pragma unroll
    for (int s = 128; s > 0; s >>= 1) {
        if (tid < s) red[tid] = fmaxf(red[tid], red[tid + s]);
        __syncthreads();
    }
    m = red[0];
    __syncthreads();

    float sum = 0.0f;
    for (int k = tid; k < L; k += 256) sum += expf(p[k] - m);
    red[tid] = sum; __syncthreads();
    #pragma unroll
    for (int s = 128; s > 0; s >>= 1) {
        if (tid < s) red[tid] += red[tid + s];
        __syncthreads();
    }
    const float inv = 1.0f / red[0];

    for (int k = tid; k < L; k += 256) {
        const float val = expf(p[k] - m) * inv;
        p[k] = val;
        const __nv_bfloat16 hi = __float2bfloat16_rn(val);
        ph[k] = hi;
        pl[k] = __float2bfloat16_rn(val - __bfloat162float(hi));
    }
}

// ---------------------------------------------------------------------------
// Pass 3: att_vec = W @ X, kmax=(ti+1)*128 for ALL tiles (row 0 fixed later)
// ---------------------------------------------------------------------------
__global__ __launch_bounds__(256, 2) void av_mma_kernel(float* __restrict__ o) {
    const int b = blockIdx.z, ti = blockIdx.y, tj = blockIdx.x;
    const int gi0 = ti * 128, gj0 = tj * 128;
    const int kmax = (ti + 1) * 128;

    float acc[4][4][4] = {};
    const size_t ao = ((size_t)b * T_ + gi0) * T_;
    const size_t bo = ((size_t)b * D_ + gj0) * T_;
    gemm_mainloop(g_whi + ao, g_wlo + ao, g_xthi + bo, g_xtlo + bo, T_, kmax, acc, false);

    float* ob = o + (size_t)b * T_ * D_;
    const int tid = threadIdx.x;
    const int lane = tid & 31, warp = tid >> 5;
    const int wm = (warp >> 2) * 64, wn = (warp & 3) * 32;
    #pragma unroll
    for (int mt = 0; mt < 4; ++mt)
        #pragma unroll
        for (int nt = 0; nt < 4; ++nt) {
            const int gi = gi0 + wm + mt * 16 + (lane >> 2);
            const int gj = gj0 + wn + nt * 8 + 2 * (lane & 3);
            float* p0 = ob + (size_t)gi * D_ + gj;
            float* p1 = ob + (size_t)(gi + 8) * D_ + gj;
            p0[0] = acc[mt][nt][0]; p0[1] = acc[mt][nt][1];
            p1[0] = acc[mt][nt][2]; p1[1] = acc[mt][nt][3];
        }
}

// ---------------------------------------------------------------------------
// Row-0 fix: av[b,0,:] = (1/T) * sum_s x[b,s,:]  (exact 2-stage reduction)
// ---------------------------------------------------------------------------
__global__ __launch_bounds__(256) void row0_partial_kernel(const float* __restrict__ x) {
    const int b = blockIdx.z, sp = blockIdx.y;       // 8 T-splits of 256 rows
    const int d = blockIdx.x * 256 + threadIdx.x;
    const float* xb = x + (size_t)b * T_ * D_ + (size_t)sp * 256 * D_ + d;
    float s = 0.0f;
    for (int r = 0; r < 256; ++r) s += xb[(size_t)r * D_];
    g_r0[((size_t)b * 8 + sp) * D_ + d] = s;
}
__global__ __launch_bounds__(256) void row0_final_kernel(float* __restrict__ o) {
    const int b = blockIdx.y;
    const int d = blockIdx.x * 256 + threadIdx.x;
    float s = 0.0f;
    #pragma unroll
    for (int j = 0; j < 8; ++j) s += g_r0[((size_t)b * 8 + j) * D_ + d];
    o[(size_t)b * T_ * D_ + d] = s * (1.0f / (float)T_);
}

// ---------------------------------------------------------------------------
extern "C" void kernel_launch(void* const* d_in, const int* in_sizes, int n_in,
                              void* d_out, int out_size) {
    const float* x = (const float*)d_in[0];
    float* att_vec = (float*)d_out;                          // [B,T,D]
    float* att_w   = (float*)d_out + (size_t)B_ * T_ * D_;   // [B,T,T]
    (void)in_sizes; (void)n_in; (void)out_size;

    cudaFuncSetAttribute(scores_mma_kernel, cudaFuncAttributeMaxDynamicSharedMemorySize, SMEM_BYTES);
    cudaFuncSetAttribute(av_mma_kernel, cudaFuncAttributeMaxDynamicSharedMemorySize, SMEM_BYTES);

    convert_kernel<<<dim3(D_ / 32, T_ / 32, B_), dim3(32, 8)>>>(x);
    scores_mma_kernel<<<dim3(T_ / 128, T_ / 128, B_), 256, SMEM_BYTES>>>(att_w);
    softmax_kernel<<<dim3(T_, B_), 256>>>(att_w);
    av_mma_kernel<<<dim3(D_ / 128, T_ / 128, B_), 256, SMEM_BYTES>>>(att_vec);
    row0_partial_kernel<<<dim3(D_ / 256, 8, B_), 256>>>(x);
    row0_final_kernel<<<dim3(D_ / 256, B_), 256>>>(att_vec);
}

// round 8
// speedup vs baseline: 1.0658x; 1.0568x over previous
#include <cuda_runtime.h>
#include <cuda_bf16.h>
#include <math.h>
#include <stdint.h>

// Attention_33492154974379:  x [B=8, T=2048, D=1024] fp32
// out = concat(att_vec [B,T,D], att_weights [B,T,T])
// R7: mma.sync (legacy HMMA rate-bound ~48%). MAC cuts from R6 kept, but the
//     diagonal-skip is now a TEMPLATE parameter so the 120 non-diag tiles/batch
//     compile to the branch-free R3 inner loop.

#define B_ 8
#define T_ 2048
#define D_ 1024
#define NEG_INF_ (-1.0e9f)

// ---- static scratch ----
__device__ __nv_bfloat16 g_xhi[(size_t)B_ * T_ * D_];
__device__ __nv_bfloat16 g_xlo[(size_t)B_ * T_ * D_];
__device__ __nv_bfloat16 g_xthi[(size_t)B_ * D_ * T_];   // x^T [B,D,T]
__device__ __nv_bfloat16 g_xtlo[(size_t)B_ * D_ * T_];
__device__ __nv_bfloat16 g_whi[(size_t)B_ * T_ * T_];
__device__ __nv_bfloat16 g_wlo[(size_t)B_ * T_ * T_];
__device__ float g_r0[(size_t)B_ * 8 * D_];              // row-0 partial sums

// ---- smem: 4 tiles (Ahi,Alo,Bhi,Blo) of 128 x 32 bf16, stride 40 ----
#define LDS_ 40
#define TILE_E (128 * LDS_)
#define STAGE_E (4 * TILE_E)
#define SMEM_BYTES (2 * STAGE_E * 2)  // 81920 B double buffered

__device__ __forceinline__ void ldsm4(uint32_t* r, uint32_t a) {
    asm volatile("ldmatrix.sync.aligned.m8n8.x4.shared.b16 {%0,%1,%2,%3}, [%4];"
                 : "=r"(r[0]), "=r"(r[1]), "=r"(r[2]), "=r"(r[3]) : "r"(a));
}
__device__ __forceinline__ void mma16816(float* d, const uint32_t* a, const uint32_t* b) {
    asm volatile("mma.sync.aligned.m16n8k16.row.col.f32.bf16.bf16.f32 "
                 "{%0,%1,%2,%3}, {%4,%5,%6,%7}, {%8,%9}, {%0,%1,%2,%3};"
                 : "+f"(d[0]), "+f"(d[1]), "+f"(d[2]), "+f"(d[3])
                 : "r"(a[0]), "r"(a[1]), "r"(a[2]), "r"(a[3]), "r"(b[0]), "r"(b[1]));
}
__device__ __forceinline__ void cpa16(uint32_t d, const void* s) {
    asm volatile("cp.async.cg.shared.global [%0], [%1], 16;" :: "r"(d), "l"(s) : "memory");
}
__device__ __forceinline__ void cpcommit() { asm volatile("cp.async.commit_group;" ::: "memory"); }
template <int N>
__device__ __forceinline__ void cpwait() { asm volatile("cp.async.wait_group %0;" :: "n"(N) : "memory"); }

// ---------------------------------------------------------------------------
// Pass 0: x -> (hi,lo) and transposed (hi,lo)
// ---------------------------------------------------------------------------
__global__ __launch_bounds__(256) void convert_kernel(const float* __restrict__ x) {
    __shared__ float tile[32][33];
    const int b = blockIdx.z;
    const int t0 = blockIdx.y * 32, d0 = blockIdx.x * 32;
    const int tx = threadIdx.x, ty = threadIdx.y;  // (32, 8)
    const float* xb = x + (size_t)b * T_ * D_;

    #pragma unroll
    for (int k = 0; k < 4; ++k) {
        const int r = ty + k * 8;
        const float v = xb[(size_t)(t0 + r) * D_ + d0 + tx];
        tile[r][tx] = v;
        __nv_bfloat16 hi = __float2bfloat16_rn(v);
        __nv_bfloat16 lo = __float2bfloat16_rn(v - __bfloat162float(hi));
        const size_t o = (size_t)b * T_ * D_ + (size_t)(t0 + r) * D_ + d0 + tx;
        g_xhi[o] = hi; g_xlo[o] = lo;
    }
    __syncthreads();
    #pragma unroll
    for (int k = 0; k < 4; ++k) {
        const int r = ty + k * 8;
        const float v = tile[tx][r];
        __nv_bfloat16 hi = __float2bfloat16_rn(v);
        __nv_bfloat16 lo = __float2bfloat16_rn(v - __bfloat162float(hi));
        const size_t o = (size_t)b * D_ * T_ + (size_t)(d0 + r) * T_ + t0 + tx;
        g_xthi[o] = hi; g_xtlo[o] = lo;
    }
}

// ---------------------------------------------------------------------------
// Shared MMA mainloop: C[128x128] += 3-term split GEMM over K (chunks of 32).
// DIAG=true instantiation skips accumulator blocks above the diagonal.
// ---------------------------------------------------------------------------
template <bool DIAG>
__device__ __forceinline__ void gemm_mainloop(
    const __nv_bfloat16* __restrict__ Ahi, const __nv_bfloat16* __restrict__ Alo,
    const __nv_bfloat16* __restrict__ Bhi, const __nv_bfloat16* __restrict__ Blo,
    int ldk, int kmax, float acc[4][4][4])
{
    extern __shared__ __nv_bfloat16 sm[];
    const int tid = threadIdx.x;
    const int lane = tid & 31, warp = tid >> 5;
    const int wm = (warp >> 2) * 64, wn = (warp & 3) * 32;
    const uint32_t smem_u32 = (uint32_t)__cvta_generic_to_shared(sm);

    const int tile = tid >> 6;
    const __nv_bfloat16* sp = (tile == 0) ? Ahi : (tile == 1) ? Alo : (tile == 2) ? Bhi : Blo;
    const int crow0 = (tid & 63) >> 2;
    const int cc = tid & 3;
    const uint32_t dtile = (uint32_t)(tile * TILE_E) * 2;

    const int nchunks = kmax >> 5;

    {
        #pragma unroll
        for (int t = 0; t < 8; ++t) {
            const int row = crow0 + t * 16;
            cpa16(smem_u32 + dtile + (uint32_t)(row * LDS_ + cc * 8) * 2,
                  sp + (size_t)row * ldk + cc * 8);
        }
        cpcommit();
    }

    for (int i = 0; i < nchunks; ++i) {
        const int s = i & 1;
        if (i + 1 < nchunks) {
            const int kk = (i + 1) << 5;
            const uint32_t dst0 = smem_u32 + (uint32_t)((s ^ 1) * STAGE_E) * 2 + dtile;
            #pragma unroll
            for (int t = 0; t < 8; ++t) {
                const int row = crow0 + t * 16;
                cpa16(dst0 + (uint32_t)(row * LDS_ + cc * 8) * 2,
                      sp + (size_t)row * ldk + kk + cc * 8);
            }
            cpcommit();
            cpwait<1>();
        } else {
            cpwait<0>();
        }
        __syncthreads();

        const uint32_t stA   = smem_u32 + (uint32_t)(s * STAGE_E) * 2;
        const uint32_t stAlo = stA + TILE_E * 2;
        const uint32_t stB   = stA + 2 * TILE_E * 2;
        const uint32_t stBlo = stA + 3 * TILE_E * 2;

        #pragma unroll
        for (int s2 = 0; s2 < 2; ++s2) {
            uint32_t ahi[4][4], alo[4][4], bhi[4][2], blo[4][2];
            const int ar = wm + (lane & 15);
            const int ac = ((lane >> 4) + 2 * s2) * 8;
            #pragma unroll
            for (int mt = 0; mt < 4; ++mt) {
                const uint32_t off = (uint32_t)((ar + mt * 16) * LDS_ + ac) * 2;
                ldsm4(ahi[mt], stA + off);
                ldsm4(alo[mt], stAlo + off);
            }
            const int br = wn + ((lane >> 4) & 1) * 8 + (lane & 7);
            const int bc = (((lane >> 3) & 1) + 2 * s2) * 8;
            #pragma unroll
            for (int p = 0; p < 2; ++p) {
                const uint32_t off = (uint32_t)((br + p * 16) * LDS_ + bc) * 2;
                uint32_t r4[4];
                ldsm4(r4, stB + off);
                bhi[2 * p][0] = r4[0]; bhi[2 * p][1] = r4[1];
                bhi[2 * p + 1][0] = r4[2]; bhi[2 * p + 1][1] = r4[3];
                ldsm4(r4, stBlo + off);
                blo[2 * p][0] = r4[0]; blo[2 * p][1] = r4[1];
                blo[2 * p + 1][0] = r4[2]; blo[2 * p + 1][1] = r4[3];
            }
            #pragma unroll
            for (int mt = 0; mt < 4; ++mt)
                #pragma unroll
                for (int nt = 0; nt < 4; ++nt) {
                    if (DIAG) {
                        // skip blocks fully above the strict-lower region
                        if (wn + nt * 8 > wm + mt * 16 + 14) continue;
                    }
                    mma16816(acc[mt][nt], ahi[mt], bhi[nt]);
                    mma16816(acc[mt][nt], ahi[mt], blo[nt]);
                    mma16816(acc[mt][nt], alo[mt], bhi[nt]);
                }
        }
        __syncthreads();
    }
}

// ---------------------------------------------------------------------------
// Pass 1: masked scores. Upper tiles get final W=0.0f (softmax skips them).
// ---------------------------------------------------------------------------
__global__ __launch_bounds__(256, 2) void scores_mma_kernel(float* __restrict__ w) {
    const int b = blockIdx.z, ti = blockIdx.y, tj = blockIdx.x;
    float* wb = w + (size_t)b * T_ * T_;
    const int gi0 = ti * 128, gj0 = tj * 128;
    const int tid = threadIdx.x;

    if (tj > ti) {  // fully masked tile: write FINAL weight value 0.0f
        const float4 zv = make_float4(0.0f, 0.0f, 0.0f, 0.0f);
        #pragma unroll
        for (int t = 0; t < 16; ++t) {
            const int i = tid + t * 256;
            const int r = i >> 5, c4 = i & 31;
            *(float4*)(wb + (size_t)(gi0 + r) * T_ + gj0 + c4 * 4) = zv;
        }
        return;
    }

    float acc[4][4][4] = {};
    const size_t ao = ((size_t)b * T_ + gi0) * D_;
    const size_t bo = ((size_t)b * T_ + gj0) * D_;
    const bool diag = (ti == tj);
    if (diag)
        gemm_mainloop<true >(g_xhi + ao, g_xlo + ao, g_xhi + bo, g_xlo + bo, D_, D_, acc);
    else
        gemm_mainloop<false>(g_xhi + ao, g_xlo + ao, g_xhi + bo, g_xlo + bo, D_, D_, acc);

    const int lane = tid & 31, warp = tid >> 5;
    const int wm = (warp >> 2) * 64, wn = (warp & 3) * 32;
    #pragma unroll
    for (int mt = 0; mt < 4; ++mt)
        #pragma unroll
        for (int nt = 0; nt < 4; ++nt) {
            const int gi = gi0 + wm + mt * 16 + (lane >> 2);
            const int gj = gj0 + wn + nt * 8 + 2 * (lane & 3);
            float* p0 = wb + (size_t)gi * T_ + gj;
            float* p1 = wb + (size_t)(gi + 8) * T_ + gj;
            if (!diag) {
                p0[0] = acc[mt][nt][0]; p0[1] = acc[mt][nt][1];
                p1[0] = acc[mt][nt][2]; p1[1] = acc[mt][nt][3];
            } else {
                p0[0] = (gj     < gi    ) ? acc[mt][nt][0] : NEG_INF_;
                p0[1] = (gj + 1 < gi    ) ? acc[mt][nt][1] : NEG_INF_;
                p1[0] = (gj     < gi + 8) ? acc[mt][nt][2] : NEG_INF_;
                p1[1] = (gj + 1 < gi + 8) ? acc[mt][nt][3] : NEG_INF_;
            }
        }
}

// ---------------------------------------------------------------------------
// Pass 2: prefix softmax (single expf, register-resident). Row i touches
// k < roundup(i+1,128). Row 0: uniform 1/T over the full row.
// ---------------------------------------------------------------------------
__global__ __launch_bounds__(256) void softmax_kernel(float* __restrict__ w) {
    const int b = blockIdx.y;
    const int i = blockIdx.x;
    const size_t row = (size_t)b * T_ + i;
    float* p = w + row * T_;
    __nv_bfloat16* ph = g_whi + row * T_;
    __nv_bfloat16* pl = g_wlo + row * T_;
    const int tid = threadIdx.x;

    if (i == 0) {
        const float val = 1.0f / (float)T_;
        const __nv_bfloat16 hi = __float2bfloat16_rn(val);
        const __nv_bfloat16 lo = __float2bfloat16_rn(val - __bfloat162float(hi));
        for (int k = tid; k < T_; k += 256) { p[k] = val; ph[k] = hi; pl[k] = lo; }
        return;
    }

    const int L = (((i >> 7) + 1) << 7);   // 128..2048, multiple of 128

    float v[8];
    float m = -INFINITY;
    #pragma unroll
    for (int j = 0; j < 8; ++j) {
        const int k = tid + j * 256;
        v[j] = (k < L) ? p[k] : NEG_INF_;
        m = fmaxf(m, v[j]);
    }

    __shared__ float red[256];
    red[tid] = m; __syncthreads();
    #pragma unroll
    for (int s = 128; s > 0; s >>= 1) {
        if (tid < s) red[tid] = fmaxf(red[tid], red[tid + s]);
        __syncthreads();
    }
    m = red[0];
    __syncthreads();

    float sum = 0.0f;
    #pragma unroll
    for (int j = 0; j < 8; ++j) { v[j] = expf(v[j] - m); sum += v[j]; }

    red[tid] = sum; __syncthreads();
    #pragma unroll
    for (int s = 128; s > 0; s >>= 1) {
        if (tid < s) red[tid] += red[tid + s];
        __syncthreads();
    }
    const float inv = 1.0f / red[0];

    #pragma unroll
    for (int j = 0; j < 8; ++j) {
        const int k = tid + j * 256;
        if (k < L) {
            const float val = v[j] * inv;
            p[k] = val;
            const __nv_bfloat16 hi = __float2bfloat16_rn(val);
            ph[k] = hi;
            pl[k] = __float2bfloat16_rn(val - __bfloat162float(hi));
        }
    }
}

// ---------------------------------------------------------------------------
// Pass 3: att_vec = W @ X, kmax=(ti+1)*128 for ALL tiles (row 0 fixed later)
// ---------------------------------------------------------------------------
__global__ __launch_bounds__(256, 2) void av_mma_kernel(float* __restrict__ o) {
    const int b = blockIdx.z, ti = blockIdx.y, tj = blockIdx.x;
    const int gi0 = ti * 128, gj0 = tj * 128;
    const int kmax = (ti + 1) * 128;

    float acc[4][4][4] = {};
    const size_t ao = ((size_t)b * T_ + gi0) * T_;
    const size_t bo = ((size_t)b * D_ + gj0) * T_;
    gemm_mainloop<false>(g_whi + ao, g_wlo + ao, g_xthi + bo, g_xtlo + bo, T_, kmax, acc);

    float* ob = o + (size_t)b * T_ * D_;
    const int tid = threadIdx.x;
    const int lane = tid & 31, warp = tid >> 5;
    const int wm = (warp >> 2) * 64, wn = (warp & 3) * 32;
    #pragma unroll
    for (int mt = 0; mt < 4; ++mt)
        #pragma unroll
        for (int nt = 0; nt < 4; ++nt) {
            const int gi = gi0 + wm + mt * 16 + (lane >> 2);
            const int gj = gj0 + wn + nt * 8 + 2 * (lane & 3);
            float* p0 = ob + (size_t)gi * D_ + gj;
            float* p1 = ob + (size_t)(gi + 8) * D_ + gj;
            p0[0] = acc[mt][nt][0]; p0[1] = acc[mt][nt][1];
            p1[0] = acc[mt][nt][2]; p1[1] = acc[mt][nt][3];
        }
}

// ---------------------------------------------------------------------------
// Row-0 fix: av[b,0,:] = (1/T) * sum_s x[b,s,:]  (exact 2-stage reduction)
// ---------------------------------------------------------------------------
__global__ __launch_bounds__(256) void row0_partial_kernel(const float* __restrict__ x) {
    const int b = blockIdx.z, sp = blockIdx.y;       // 8 T-splits of 256 rows
    const int d = blockIdx.x * 256 + threadIdx.x;
    const float* xb = x + (size_t)b * T_ * D_ + (size_t)sp * 256 * D_ + d;
    float s = 0.0f;
    for (int r = 0; r < 256; ++r) s += xb[(size_t)r * D_];
    g_r0[((size_t)b * 8 + sp) * D_ + d] = s;
}
__global__ __launch_bounds__(256) void row0_final_kernel(float* __restrict__ o) {
    const int b = blockIdx.y;
    const int d = blockIdx.x * 256 + threadIdx.x;
    float s = 0.0f;
    #pragma unroll
    for (int j = 0; j < 8; ++j) s += g_r0[((size_t)b * 8 + j) * D_ + d];
    o[(size_t)b * T_ * D_ + d] = s * (1.0f / (float)T_);
}

// ---------------------------------------------------------------------------
extern "C" void kernel_launch(void* const* d_in, const int* in_sizes, int n_in,
                              void* d_out, int out_size) {
    const float* x = (const float*)d_in[0];
    float* att_vec = (float*)d_out;                          // [B,T,D]
    float* att_w   = (float*)d_out + (size_t)B_ * T_ * D_;   // [B,T,T]
    (void)in_sizes; (void)n_in; (void)out_size;

    cudaFuncSetAttribute(scores_mma_kernel, cudaFuncAttributeMaxDynamicSharedMemorySize, SMEM_BYTES);
    cudaFuncSetAttribute(av_mma_kernel, cudaFuncAttributeMaxDynamicSharedMemorySize, SMEM_BYTES);

    convert_kernel<<<dim3(D_ / 32, T_ / 32, B_), dim3(32, 8)>>>(x);
    scores_mma_kernel<<<dim3(T_ / 128, T_ / 128, B_), 256, SMEM_BYTES>>>(att_w);
    softmax_kernel<<<dim3(T_, B_), 256>>>(att_w);
    av_mma_kernel<<<dim3(D_ / 128, T_ / 128, B_), 256, SMEM_BYTES>>>(att_vec);
    row0_partial_kernel<<<dim3(D_ / 256, 8, B_), 256>>>(x);
    row0_final_kernel<<<dim3(D_ / 256, B_), 256>>>(att_vec);
}